// round 13
// baseline (speedup 1.0000x reference)
#include <cuda_runtime.h>
#include <cuda_fp16.h>
#include <math.h>

#define NMAX 100000
#define EMAX 1600000
#define HEADS 8

typedef unsigned long long ull;
typedef unsigned int uint;

// ---------------- scratch (static device globals; no runtime alloc) ----------------
__device__ __half g_xh1[(size_t)NMAX * 256];
__device__ __half g_xh2[(size_t)NMAX * 128];
__device__ float  g_agg1[(size_t)NMAX * 32];
__device__ float  g_agg2[(size_t)NMAX * 16];
__device__ float  g_asrc[(size_t)NMAX * HEADS];
__device__ float  g_adst[(size_t)NMAX * HEADS];
__device__ float  g_den[(size_t)2 * NMAX * HEADS];
__device__ float  g_ex[(size_t)(EMAX + NMAX) * HEADS];

// ---------------- helpers ----------------
__device__ __forceinline__ void red_add_v4(float* p, float4 v) {
    asm volatile("red.global.add.v4.f32 [%0], {%1,%2,%3,%4};"
                 :: "l"(p), "f"(v.x), "f"(v.y), "f"(v.z), "f"(v.w)
                 : "memory");
}
__device__ __forceinline__ float lrelu_exp(float v) {
    v = v > 0.0f ? v : 0.2f * v;
    return __expf(v);
}
__device__ __forceinline__ void mma_f16(float* d, const uint* a, const uint* b) {
    asm("mma.sync.aligned.m16n8k16.row.col.f32.f16.f16.f32 "
        "{%0,%1,%2,%3}, {%4,%5,%6,%7}, {%8,%9}, {%0,%1,%2,%3};"
        : "+f"(d[0]), "+f"(d[1]), "+f"(d[2]), "+f"(d[3])
        : "r"(a[0]), "r"(a[1]), "r"(a[2]), "r"(a[3]), "r"(b[0]), "r"(b[1]));
}
__device__ __forceinline__ void ldsm_x4(uint* r, uint addr) {
    asm volatile("ldmatrix.sync.aligned.m8n8.x4.shared.b16 {%0,%1,%2,%3}, [%4];"
                 : "=r"(r[0]), "=r"(r[1]), "=r"(r[2]), "=r"(r[3]) : "r"(addr));
}
__device__ __forceinline__ void ldsm_x4_t(uint* r, uint addr) {
    asm volatile("ldmatrix.sync.aligned.m8n8.x4.trans.shared.b16 {%0,%1,%2,%3}, [%4];"
                 : "=r"(r[0]), "=r"(r[1]), "=r"(r[2]), "=r"(r[3]) : "r"(addr));
}
__device__ __forceinline__ uint pack_h2(float x, float y) {
    __half2 h = __floats2half2_rn(x, y);
    return *reinterpret_cast<uint*>(&h);
}

// ---------------- combined zero kernel ----------------
__global__ void zero_all_kernel(float* __restrict__ den, float* __restrict__ agg1,
                                float* __restrict__ agg2, int N) {
    int i = blockIdx.x * blockDim.x + threadIdx.x;
    if (i < 2 * N * 8) den[i] = 0.f;
    if (i < N * 32) agg1[i] = 0.f;
    if (i < N * 16) agg2[i] = 0.f;
}

// ---------------- FP16 tensor-core GEMM (ldmatrix) + attention logits ----------------
template<int F, int CO, int HS, int KC, bool ELU>
__global__ void __launch_bounds__(256, 2)
gemm_att_kernel(const float* __restrict__ X, const float* __restrict__ W,
                const float* __restrict__ a_src_w, const float* __restrict__ a_dst_w,
                const float* __restrict__ BIAS,
                __half* __restrict__ XH, float* __restrict__ ASRC,
                float* __restrict__ ADST, int N) {
    constexpr int XSH = KC + 8;
    constexpr int WSH = 136;
    constexpr int NH  = 64 / HS;
    constexpr int TPH = HS / 8;

    extern __shared__ __half shh[];
    __half* Xs = shh;
    __half* Ws = shh + 128 * XSH;

    const int tid  = threadIdx.x;
    const int lane = tid & 31;
    const int w    = tid >> 5;
    const int gid  = lane >> 2;
    const int tig  = lane & 3;
    const int wr   = (w & 3) * 32;
    const int wc   = (w >> 2) * 64;
    const int qy   = blockIdx.y;
    const int n0   = blockIdx.x * 128;

    const uint xs_base = (uint)__cvta_generic_to_shared(Xs);
    const uint ws_base = (uint)__cvta_generic_to_shared(Ws);
    const int lm = lane >> 3;
    const int lr = lane & 7;

    float d[2][8][4];
    #pragma unroll
    for (int mt = 0; mt < 2; mt++)
        #pragma unroll
        for (int nt = 0; nt < 8; nt++)
            #pragma unroll
            for (int i = 0; i < 4; i++) d[mt][nt][i] = 0.f;

    const float4* Xg4 = reinterpret_cast<const float4*>(X);
    const float4* Wg4 = reinterpret_cast<const float4*>(W);

    for (int k0 = 0; k0 < F; k0 += KC) {
        if (k0) __syncthreads();
        for (int i = tid; i < KC * 32; i += 256) {
            int kf = i >> 5, c4 = i & 31;
            float4 v = Wg4[(size_t)(k0 + kf) * (CO / 4) + qy * 32 + c4];
            uint2 u = make_uint2(pack_h2(v.x, v.y), pack_h2(v.z, v.w));
            *reinterpret_cast<uint2*>(Ws + kf * WSH + c4 * 4) = u;
        }
        for (int i = tid; i < 128 * (KC / 4); i += 256) {
            int row = i / (KC / 4), j = i % (KC / 4);
            int n = n0 + row;
            float4 v = (n < N) ? Xg4[(size_t)n * (F / 4) + (k0 / 4) + j]
                               : make_float4(0.f, 0.f, 0.f, 0.f);
            if (ELU) {
                float4 bv = __ldg(reinterpret_cast<const float4*>(BIAS) + (k0 / 4) + j);
                float m;
                m = v.x * 0.125f + bv.x; v.x = m > 0.f ? m : __expf(m) - 1.0f;
                m = v.y * 0.125f + bv.y; v.y = m > 0.f ? m : __expf(m) - 1.0f;
                m = v.z * 0.125f + bv.z; v.z = m > 0.f ? m : __expf(m) - 1.0f;
                m = v.w * 0.125f + bv.w; v.w = m > 0.f ? m : __expf(m) - 1.0f;
            }
            uint2 u = make_uint2(pack_h2(v.x, v.y), pack_h2(v.z, v.w));
            *reinterpret_cast<uint2*>(Xs + row * XSH + j * 4) = u;
        }
        __syncthreads();

        #pragma unroll
        for (int kk = 0; kk < KC; kk += 16) {
            uint a[2][4];
            #pragma unroll
            for (int mt = 0; mt < 2; mt++) {
                int row = wr + mt * 16 + (lm & 1) * 8 + lr;
                int kc  = kk + (lm >> 1) * 8;
                ldsm_x4(a[mt], xs_base + (row * XSH + kc) * 2);
            }
            uint b[8][2];
            #pragma unroll
            for (int np = 0; np < 4; np++) {
                uint rb[4];
                int kr = kk + (lm & 1) * 8 + lr;
                int nc = wc + np * 16 + (lm >> 1) * 8;
                ldsm_x4_t(rb, ws_base + (kr * WSH + nc) * 2);
                b[np * 2][0]     = rb[0]; b[np * 2][1]     = rb[1];
                b[np * 2 + 1][0] = rb[2]; b[np * 2 + 1][1] = rb[3];
            }
            #pragma unroll
            for (int nt = 0; nt < 8; nt++) {
                mma_f16(d[0][nt], a[0], b[nt]);
                mma_f16(d[1][nt], a[1], b[nt]);
            }
        }
    }

    float avs[16], avd[16];
    #pragma unroll
    for (int nt = 0; nt < 8; nt++) {
        int idx = qy * 128 + wc + nt * 8 + tig * 2;
        avs[nt * 2]     = __ldg(a_src_w + idx);
        avs[nt * 2 + 1] = __ldg(a_src_w + idx + 1);
        avd[nt * 2]     = __ldg(a_dst_w + idx);
        avd[nt * 2 + 1] = __ldg(a_dst_w + idx + 1);
    }

    #pragma unroll
    for (int mt = 0; mt < 2; mt++) {
        #pragma unroll
        for (int h2 = 0; h2 < 2; h2++) {
            int n = n0 + wr + mt * 16 + gid + h2 * 8;
            float ps[NH], pd[NH];
            #pragma unroll
            for (int hw = 0; hw < NH; hw++) { ps[hw] = 0.f; pd[hw] = 0.f; }
            #pragma unroll
            for (int nt = 0; nt < 8; nt++) {
                int hw = nt / TPH;
                float o0 = d[mt][nt][h2 * 2];
                float o1 = d[mt][nt][h2 * 2 + 1];
                ps[hw] += o0 * avs[nt * 2] + o1 * avs[nt * 2 + 1];
                pd[hw] += o0 * avd[nt * 2] + o1 * avd[nt * 2 + 1];
            }
            #pragma unroll
            for (int hw = 0; hw < NH; hw++) {
                ps[hw] += __shfl_xor_sync(0xffffffffu, ps[hw], 1);
                ps[hw] += __shfl_xor_sync(0xffffffffu, ps[hw], 2);
                pd[hw] += __shfl_xor_sync(0xffffffffu, pd[hw], 1);
                pd[hw] += __shfl_xor_sync(0xffffffffu, pd[hw], 2);
            }
            if (n < N) {
                #pragma unroll
                for (int nt = 0; nt < 8; nt++) {
                    __half2 hv = __floats2half2_rn(d[mt][nt][h2 * 2], d[mt][nt][h2 * 2 + 1]);
                    *reinterpret_cast<__half2*>(XH + (size_t)n * CO + qy * 128 + wc + nt * 8 + tig * 2) = hv;
                }
                if (tig == 0) {
                    #pragma unroll
                    for (int hw = 0; hw < NH; hw++) {
                        int h = (qy * 128 + wc) / HS + hw;
                        ASRC[(size_t)n * HEADS + h] = ps[hw];
                        ADST[(size_t)n * HEADS + h] = pd[hw];
                    }
                }
            }
        }
    }
}

// ---------------- denominator pass: compute ex once, store (streaming) + reduce den ----------------
__global__ void den_kernel(const int* __restrict__ ei, int E, int N,
                           const float* __restrict__ ASRC, const float* __restrict__ ADST,
                           float* __restrict__ EX, float* __restrict__ DEN) {
    int k = blockIdx.x * blockDim.x + threadIdx.x;
    int EN = E + N;
    if (k >= EN) return;
    int src, dst;
    if (k < E) { src = __ldg(ei + k); dst = __ldg(ei + E + k); }
    else       { src = dst = k - E; }

    float4 a0 = __ldg(reinterpret_cast<const float4*>(ASRC) + (size_t)src * 2 + 0);
    float4 a1 = __ldg(reinterpret_cast<const float4*>(ASRC) + (size_t)src * 2 + 1);
    float4 b0 = __ldg(reinterpret_cast<const float4*>(ADST) + (size_t)dst * 2 + 0);
    float4 b1 = __ldg(reinterpret_cast<const float4*>(ADST) + (size_t)dst * 2 + 1);

    float4 e0, e1;
    e0.x = lrelu_exp(a0.x + b0.x); e0.y = lrelu_exp(a0.y + b0.y);
    e0.z = lrelu_exp(a0.z + b0.z); e0.w = lrelu_exp(a0.w + b0.w);
    e1.x = lrelu_exp(a1.x + b1.x); e1.y = lrelu_exp(a1.y + b1.y);
    e1.z = lrelu_exp(a1.z + b1.z); e1.w = lrelu_exp(a1.w + b1.w);

    __stcs(reinterpret_cast<float4*>(EX) + (size_t)k * 2 + 0, e0);
    __stcs(reinterpret_cast<float4*>(EX) + (size_t)k * 2 + 1, e1);

    red_add_v4(DEN + (size_t)dst * 8 + 0, e0);
    red_add_v4(DEN + (size_t)dst * 8 + 4, e1);
}

// ---------------- aggregate layer 1: 8 lanes/edge; coalesced EX load ----------------
__global__ void aggregate1_kernel(const int* __restrict__ ei, int E, int N,
                                  const __half* __restrict__ XH,
                                  const float* __restrict__ EX,
                                  const float* __restrict__ DEN, float* __restrict__ AGG) {
    int t = blockIdx.x * blockDim.x + threadIdx.x;
    int k = t >> 3;
    int l = t & 7;
    int EN = E + N;
    bool valid = k < EN;
    if (!valid) k = 0;
    int src, dst;
    if (k < E) { src = __ldg(ei + k); dst = __ldg(ei + E + k); }
    else       { src = dst = k - E; }

    float ex = __ldcs(EX + (size_t)k * 8 + l);
    float a  = __fdividef(ex, __ldg(DEN + (size_t)dst * 8 + l));

    const uint4* xs = reinterpret_cast<const uint4*>(XH) + (size_t)src * 32;
    float acc[8];
    #pragma unroll
    for (int i = 0; i < 8; i++) acc[i] = 0.f;

    #pragma unroll
    for (int j = 0; j < 4; j++) {
        float al = __shfl_sync(0xffffffffu, a, (l >> 2) + 2 * j, 8);
        uint4 u = __ldg(xs + l + 8 * j);
        float2 f0 = __half22float2(*reinterpret_cast<__half2*>(&u.x));
        float2 f1 = __half22float2(*reinterpret_cast<__half2*>(&u.y));
        float2 f2 = __half22float2(*reinterpret_cast<__half2*>(&u.z));
        float2 f3 = __half22float2(*reinterpret_cast<__half2*>(&u.w));
        acc[0] += al * f0.x; acc[1] += al * f0.y;
        acc[2] += al * f1.x; acc[3] += al * f1.y;
        acc[4] += al * f2.x; acc[5] += al * f2.y;
        acc[6] += al * f3.x; acc[7] += al * f3.y;
    }
    #pragma unroll
    for (int i = 0; i < 8; i++) acc[i] += __shfl_xor_sync(0xffffffffu, acc[i], 4);
    if (valid && l < 4) {
        float* ag = AGG + (size_t)dst * 32 + l * 8;
        red_add_v4(ag,     make_float4(acc[0], acc[1], acc[2], acc[3]));
        red_add_v4(ag + 4, make_float4(acc[4], acc[5], acc[6], acc[7]));
    }
}

// ---------------- aggregate layer 2: 4 lanes/edge; coalesced EX load ----------------
__global__ void aggregate2_kernel(const int* __restrict__ ei, int E, int N,
                                  const __half* __restrict__ XH,
                                  const float* __restrict__ EX,
                                  const float* __restrict__ DEN, float* __restrict__ AGG) {
    int t = blockIdx.x * blockDim.x + threadIdx.x;
    int k = t >> 2;
    int l = t & 3;
    int EN = E + N;
    bool valid = k < EN;
    if (!valid) k = 0;
    int src, dst;
    if (k < E) { src = __ldg(ei + k); dst = __ldg(ei + E + k); }
    else       { src = dst = k - E; }

    float ex0 = __ldcs(EX + (size_t)k * 8 + l);
    float ex1 = __ldcs(EX + (size_t)k * 8 + l + 4);
    float a0 = __fdividef(ex0, __ldg(DEN + (size_t)dst * 8 + l));
    float a1 = __fdividef(ex1, __ldg(DEN + (size_t)dst * 8 + l + 4));

    const uint4* xs = reinterpret_cast<const uint4*>(XH) + (size_t)src * 16;
    float acc[8];
    #pragma unroll
    for (int i = 0; i < 8; i++) acc[i] = 0.f;

    #pragma unroll
    for (int j = 0; j < 4; j++) {
        float al;
        if (j == 0)      al = __shfl_sync(0xffffffffu, a0, (l >> 1),     4);
        else if (j == 1) al = __shfl_sync(0xffffffffu, a0, (l >> 1) + 2, 4);
        else if (j == 2) al = __shfl_sync(0xffffffffu, a1, (l >> 1),     4);
        else             al = __shfl_sync(0xffffffffu, a1, (l >> 1) + 2, 4);
        uint4 u = __ldg(xs + l + 4 * j);
        float2 f0 = __half22float2(*reinterpret_cast<__half2*>(&u.x));
        float2 f1 = __half22float2(*reinterpret_cast<__half2*>(&u.y));
        float2 f2 = __half22float2(*reinterpret_cast<__half2*>(&u.z));
        float2 f3 = __half22float2(*reinterpret_cast<__half2*>(&u.w));
        acc[0] += al * f0.x; acc[1] += al * f0.y;
        acc[2] += al * f1.x; acc[3] += al * f1.y;
        acc[4] += al * f2.x; acc[5] += al * f2.y;
        acc[6] += al * f3.x; acc[7] += al * f3.y;
    }
    #pragma unroll
    for (int i = 0; i < 8; i++) acc[i] += __shfl_xor_sync(0xffffffffu, acc[i], 2);
    if (valid && l < 2) {
        float* ag = AGG + (size_t)dst * 16 + l * 8;
        red_add_v4(ag,     make_float4(acc[0], acc[1], acc[2], acc[3]));
        red_add_v4(ag + 4, make_float4(acc[4], acc[5], acc[6], acc[7]));
    }
}

// ---------------- finalize layer 2 ----------------
__global__ void finalize2_kernel(const float* __restrict__ agg, const float* __restrict__ b,
                                 float* __restrict__ outLsm, float* __restrict__ outLogits,
                                 int N, int writeLogits) {
    int gid = blockIdx.x * blockDim.x + threadIdx.x;
    int n = gid >> 4, c = gid & 15;
    bool valid = n < N;
    float l = 0.f;
    if (valid) l = agg[gid] * 0.125f + __ldg(b + c);
    float m = l;
    #pragma unroll
    for (int s = 8; s > 0; s >>= 1) m = fmaxf(m, __shfl_xor_sync(0xffffffffu, m, s));
    float e = __expf(l - m);
    float se = e;
    #pragma unroll
    for (int s = 8; s > 0; s >>= 1) se += __shfl_xor_sync(0xffffffffu, se, s);
    if (valid) {
        outLsm[gid] = l - m - logf(se);
        if (writeLogits) outLogits[gid] = l;
    }
}

// ---------------- host launcher ----------------
extern "C" void kernel_launch(void* const* d_in, const int* in_sizes, int n_in,
                              void* d_out, int out_size) {
    const float* x   = (const float*)d_in[0];
    const int*   ei  = (const int*)d_in[1];
    const float* W1  = (const float*)d_in[2];
    const float* as1 = (const float*)d_in[3];
    const float* ad1 = (const float*)d_in[4];
    const float* b1  = (const float*)d_in[5];
    const float* W2  = (const float*)d_in[6];
    const float* as2 = (const float*)d_in[7];
    const float* ad2 = (const float*)d_in[8];
    const float* b2  = (const float*)d_in[9];

    int N  = in_sizes[0] / 128;
    int E  = in_sizes[1] / 2;
    int EN = E + N;
    float* out = (float*)d_out;

    void *xh1, *xh2, *agg1, *agg2, *asrc, *adst, *den, *exb;
    cudaGetSymbolAddress(&xh1,  g_xh1);
    cudaGetSymbolAddress(&xh2,  g_xh2);
    cudaGetSymbolAddress(&agg1, g_agg1);
    cudaGetSymbolAddress(&agg2, g_agg2);
    cudaGetSymbolAddress(&asrc, g_asrc);
    cudaGetSymbolAddress(&adst, g_adst);
    cudaGetSymbolAddress(&den,  g_den);
    cudaGetSymbolAddress(&exb,  g_ex);

    float* den1 = (float*)den;
    float* den2 = (float*)den + (size_t)N * 8;
    float* EX   = (float*)exb;

    const int smem1 = (128 * (64 + 8) + 64 * 136) * 2;   // 35840 B
    const int smem2 = (128 * (32 + 8) + 32 * 136) * 2;   // 18944 B
    cudaFuncSetAttribute(gemm_att_kernel<128, 256, 32, 64, false>,
                         cudaFuncAttributeMaxDynamicSharedMemorySize, smem1);
    cudaFuncSetAttribute(gemm_att_kernel<32, 128, 16, 32, true>,
                         cudaFuncAttributeMaxDynamicSharedMemorySize, smem2);

    // 1: zero everything
    zero_all_kernel<<<(N * 32 + 255) / 256, 256>>>((float*)den, (float*)agg1, (float*)agg2, N);

    // ---- layer 1 ----
    gemm_att_kernel<128, 256, 32, 64, false><<<dim3((N + 127) / 128, 2), 256, smem1>>>(
        x, W1, as1, ad1, nullptr, (__half*)xh1, (float*)asrc, (float*)adst, N);        // 2
    den_kernel<<<(EN + 255) / 256, 256>>>(ei, E, N, (float*)asrc, (float*)adst, EX, den1); // 3
    aggregate1_kernel<<<((size_t)EN * 8 + 255) / 256, 256>>>(
        ei, E, N, (__half*)xh1, EX, den1, (float*)agg1);                               // 4 <- profiled

    // ---- layer 2 ----
    gemm_att_kernel<32, 128, 16, 32, true><<<dim3((N + 127) / 128, 1), 256, smem2>>>(
        (float*)agg1, W2, as2, ad2, b1, (__half*)xh2, (float*)asrc, (float*)adst, N);  // 5
    den_kernel<<<(EN + 255) / 256, 256>>>(ei, E, N, (float*)asrc, (float*)adst, EX, den2); // 6
    aggregate2_kernel<<<((size_t)EN * 4 + 255) / 256, 256>>>(
        ei, E, N, (__half*)xh2, EX, den2, (float*)agg2);                               // 7

    int wl = (out_size >= 2 * N * 16) ? 1 : 0;
    finalize2_kernel<<<(N * 16 + 127) / 128, 128>>>((float*)agg2, b2,
                                                    out, out + (size_t)N * 16, N, wl); // 8
}

// round 14
// speedup vs baseline: 1.0854x; 1.0854x over previous
#include <cuda_runtime.h>
#include <cuda_fp16.h>
#include <math.h>

#define NMAX 100000
#define EMAX 1600000
#define HEADS 8

typedef unsigned long long ull;
typedef unsigned int uint;

// ---------------- scratch (static device globals; no runtime alloc) ----------------
__device__ __half g_xh1[(size_t)NMAX * 256];
__device__ __half g_xh2[(size_t)NMAX * 128];
__device__ float  g_agg1[(size_t)NMAX * 32];
__device__ float  g_agg2[(size_t)NMAX * 16];
__device__ float  g_asrc[(size_t)NMAX * HEADS];
__device__ float  g_adst[(size_t)NMAX * HEADS];
__device__ float  g_den[(size_t)2 * NMAX * HEADS];

// ---------------- helpers ----------------
__device__ __forceinline__ void red_add_v4(float* p, float4 v) {
    asm volatile("red.global.add.v4.f32 [%0], {%1,%2,%3,%4};"
                 :: "l"(p), "f"(v.x), "f"(v.y), "f"(v.z), "f"(v.w)
                 : "memory");
}
__device__ __forceinline__ float lrelu_exp(float v) {
    v = v > 0.0f ? v : 0.2f * v;
    return __expf(v);
}
__device__ __forceinline__ void mma_f16(float* d, const uint* a, const uint* b) {
    asm("mma.sync.aligned.m16n8k16.row.col.f32.f16.f16.f32 "
        "{%0,%1,%2,%3}, {%4,%5,%6,%7}, {%8,%9}, {%0,%1,%2,%3};"
        : "+f"(d[0]), "+f"(d[1]), "+f"(d[2]), "+f"(d[3])
        : "r"(a[0]), "r"(a[1]), "r"(a[2]), "r"(a[3]), "r"(b[0]), "r"(b[1]));
}
__device__ __forceinline__ void ldsm_x4(uint* r, uint addr) {
    asm volatile("ldmatrix.sync.aligned.m8n8.x4.shared.b16 {%0,%1,%2,%3}, [%4];"
                 : "=r"(r[0]), "=r"(r[1]), "=r"(r[2]), "=r"(r[3]) : "r"(addr));
}
__device__ __forceinline__ void ldsm_x4_t(uint* r, uint addr) {
    asm volatile("ldmatrix.sync.aligned.m8n8.x4.trans.shared.b16 {%0,%1,%2,%3}, [%4];"
                 : "=r"(r[0]), "=r"(r[1]), "=r"(r[2]), "=r"(r[3]) : "r"(addr));
}
__device__ __forceinline__ uint pack_h2(float x, float y) {
    __half2 h = __floats2half2_rn(x, y);
    return *reinterpret_cast<uint*>(&h);
}

// ---------------- combined zero kernel ----------------
__global__ void zero_all_kernel(float* __restrict__ den, float* __restrict__ agg1,
                                float* __restrict__ agg2, int N) {
    int i = blockIdx.x * blockDim.x + threadIdx.x;
    if (i < 2 * N * 8) den[i] = 0.f;
    if (i < N * 32) agg1[i] = 0.f;
    if (i < N * 16) agg2[i] = 0.f;
}

// ---------------- FP16 tensor-core GEMM (ldmatrix) + attention logits ----------------
// 256 threads (8 warps: 4 row x 2 col). Block tile: 128 rows x 64 cols (3 blocks/SM).
// Warp tile: 32 rows (2 m16) x 32 cols (4 n8). CO split across gridDim.y slices of 64.
template<int F, int CO, int HS, int KC, bool ELU>
__global__ void __launch_bounds__(256, 3)
gemm_att_kernel(const float* __restrict__ X, const float* __restrict__ W,
                const float* __restrict__ a_src_w, const float* __restrict__ a_dst_w,
                const float* __restrict__ BIAS,
                __half* __restrict__ XH, float* __restrict__ ASRC,
                float* __restrict__ ADST, int N) {
    constexpr int XSH = KC + 8;
    constexpr int WSH = 72;          // 64 cols + 8 pad (halves)
    constexpr int NH  = 32 / HS;     // heads per warp-col-span
    constexpr int TPH = HS / 8;      // n8-tiles per head

    extern __shared__ __half shh[];
    __half* Xs = shh;                    // [128][XSH]
    __half* Ws = shh + 128 * XSH;        // [KC][WSH]

    const int tid  = threadIdx.x;
    const int lane = tid & 31;
    const int w    = tid >> 5;
    const int gid  = lane >> 2;
    const int tig  = lane & 3;
    const int wr   = (w & 3) * 32;
    const int wc   = (w >> 2) * 32;
    const int qy   = blockIdx.y;
    const int n0   = blockIdx.x * 128;

    const uint xs_base = (uint)__cvta_generic_to_shared(Xs);
    const uint ws_base = (uint)__cvta_generic_to_shared(Ws);
    const int lm = lane >> 3;
    const int lr = lane & 7;

    float d[2][4][4];
    #pragma unroll
    for (int mt = 0; mt < 2; mt++)
        #pragma unroll
        for (int nt = 0; nt < 4; nt++)
            #pragma unroll
            for (int i = 0; i < 4; i++) d[mt][nt][i] = 0.f;

    const float4* Xg4 = reinterpret_cast<const float4*>(X);
    const float4* Wg4 = reinterpret_cast<const float4*>(W);

    for (int k0 = 0; k0 < F; k0 += KC) {
        if (k0) __syncthreads();
        // load W chunk [KC][64 cols] -> Ws[k][n] fp16
        for (int i = tid; i < KC * 16; i += 256) {
            int kf = i >> 4, c4 = i & 15;
            float4 v = Wg4[(size_t)(k0 + kf) * (CO / 4) + qy * 16 + c4];
            uint2 u = make_uint2(pack_h2(v.x, v.y), pack_h2(v.z, v.w));
            *reinterpret_cast<uint2*>(Ws + kf * WSH + c4 * 4) = u;
        }
        // load X chunk [128][KC] -> Xs[row][k] fp16 (with optional ELU transform)
        for (int i = tid; i < 128 * (KC / 4); i += 256) {
            int row = i / (KC / 4), j = i % (KC / 4);
            int n = n0 + row;
            float4 v = (n < N) ? Xg4[(size_t)n * (F / 4) + (k0 / 4) + j]
                               : make_float4(0.f, 0.f, 0.f, 0.f);
            if (ELU) {
                float4 bv = __ldg(reinterpret_cast<const float4*>(BIAS) + (k0 / 4) + j);
                float m;
                m = v.x * 0.125f + bv.x; v.x = m > 0.f ? m : __expf(m) - 1.0f;
                m = v.y * 0.125f + bv.y; v.y = m > 0.f ? m : __expf(m) - 1.0f;
                m = v.z * 0.125f + bv.z; v.z = m > 0.f ? m : __expf(m) - 1.0f;
                m = v.w * 0.125f + bv.w; v.w = m > 0.f ? m : __expf(m) - 1.0f;
            }
            uint2 u = make_uint2(pack_h2(v.x, v.y), pack_h2(v.z, v.w));
            *reinterpret_cast<uint2*>(Xs + row * XSH + j * 4) = u;
        }
        __syncthreads();

        #pragma unroll
        for (int kk = 0; kk < KC; kk += 16) {
            uint a[2][4];
            #pragma unroll
            for (int mt = 0; mt < 2; mt++) {
                int row = wr + mt * 16 + (lm & 1) * 8 + lr;
                int kc  = kk + (lm >> 1) * 8;
                ldsm_x4(a[mt], xs_base + (row * XSH + kc) * 2);
            }
            uint b[4][2];
            #pragma unroll
            for (int np = 0; np < 2; np++) {
                uint rb[4];
                int kr = kk + (lm & 1) * 8 + lr;
                int nc = wc + np * 16 + (lm >> 1) * 8;
                ldsm_x4_t(rb, ws_base + (kr * WSH + nc) * 2);
                b[np * 2][0]     = rb[0]; b[np * 2][1]     = rb[1];
                b[np * 2 + 1][0] = rb[2]; b[np * 2 + 1][1] = rb[3];
            }
            #pragma unroll
            for (int nt = 0; nt < 4; nt++) {
                mma_f16(d[0][nt], a[0], b[nt]);
                mma_f16(d[1][nt], a[1], b[nt]);
            }
        }
    }

    // ---- epilogue: attention dots + fp16 store ----
    float avs[8], avd[8];
    #pragma unroll
    for (int nt = 0; nt < 4; nt++) {
        int idx = qy * 64 + wc + nt * 8 + tig * 2;
        avs[nt * 2]     = __ldg(a_src_w + idx);
        avs[nt * 2 + 1] = __ldg(a_src_w + idx + 1);
        avd[nt * 2]     = __ldg(a_dst_w + idx);
        avd[nt * 2 + 1] = __ldg(a_dst_w + idx + 1);
    }

    #pragma unroll
    for (int mt = 0; mt < 2; mt++) {
        #pragma unroll
        for (int h2 = 0; h2 < 2; h2++) {
            int n = n0 + wr + mt * 16 + gid + h2 * 8;
            float ps[NH], pd[NH];
            #pragma unroll
            for (int hw = 0; hw < NH; hw++) { ps[hw] = 0.f; pd[hw] = 0.f; }
            #pragma unroll
            for (int nt = 0; nt < 4; nt++) {
                int hw = nt / TPH;
                float o0 = d[mt][nt][h2 * 2];
                float o1 = d[mt][nt][h2 * 2 + 1];
                ps[hw] += o0 * avs[nt * 2] + o1 * avs[nt * 2 + 1];
                pd[hw] += o0 * avd[nt * 2] + o1 * avd[nt * 2 + 1];
            }
            #pragma unroll
            for (int hw = 0; hw < NH; hw++) {
                ps[hw] += __shfl_xor_sync(0xffffffffu, ps[hw], 1);
                ps[hw] += __shfl_xor_sync(0xffffffffu, ps[hw], 2);
                pd[hw] += __shfl_xor_sync(0xffffffffu, pd[hw], 1);
                pd[hw] += __shfl_xor_sync(0xffffffffu, pd[hw], 2);
            }
            if (n < N) {
                #pragma unroll
                for (int nt = 0; nt < 4; nt++) {
                    __half2 hv = __floats2half2_rn(d[mt][nt][h2 * 2], d[mt][nt][h2 * 2 + 1]);
                    *reinterpret_cast<__half2*>(XH + (size_t)n * CO + qy * 64 + wc + nt * 8 + tig * 2) = hv;
                }
                if (tig == 0) {
                    #pragma unroll
                    for (int hw = 0; hw < NH; hw++) {
                        int h = (qy * 64 + wc) / HS + hw;
                        ASRC[(size_t)n * HEADS + h] = ps[hw];
                        ADST[(size_t)n * HEADS + h] = pd[hw];
                    }
                }
            }
        }
    }
}

// ---------------- denominator pass ----------------
__global__ void den_kernel(const int* __restrict__ ei, int E, int N,
                           const float* __restrict__ ASRC, const float* __restrict__ ADST,
                           float* __restrict__ DEN) {
    int k = blockIdx.x * blockDim.x + threadIdx.x;
    int EN = E + N;
    if (k >= EN) return;
    int src, dst;
    if (k < E) { src = __ldg(ei + k); dst = __ldg(ei + E + k); }
    else       { src = dst = k - E; }

    float4 a0 = __ldg(reinterpret_cast<const float4*>(ASRC) + (size_t)src * 2 + 0);
    float4 a1 = __ldg(reinterpret_cast<const float4*>(ASRC) + (size_t)src * 2 + 1);
    float4 b0 = __ldg(reinterpret_cast<const float4*>(ADST) + (size_t)dst * 2 + 0);
    float4 b1 = __ldg(reinterpret_cast<const float4*>(ADST) + (size_t)dst * 2 + 1);

    float4 e0, e1;
    e0.x = lrelu_exp(a0.x + b0.x); e0.y = lrelu_exp(a0.y + b0.y);
    e0.z = lrelu_exp(a0.z + b0.z); e0.w = lrelu_exp(a0.w + b0.w);
    e1.x = lrelu_exp(a1.x + b1.x); e1.y = lrelu_exp(a1.y + b1.y);
    e1.z = lrelu_exp(a1.z + b1.z); e1.w = lrelu_exp(a1.w + b1.w);

    red_add_v4(DEN + (size_t)dst * 8 + 0, e0);
    red_add_v4(DEN + (size_t)dst * 8 + 4, e1);
}

// ---------------- aggregate layer 1: 8 lanes/edge; single red.v4 per lane ----------------
__global__ void aggregate1_kernel(const int* __restrict__ ei, int E, int N,
                                  const __half* __restrict__ XH,
                                  const float* __restrict__ ASRC, const float* __restrict__ ADST,
                                  const float* __restrict__ DEN, float* __restrict__ AGG) {
    int t = blockIdx.x * blockDim.x + threadIdx.x;
    int k = t >> 3;
    int l = t & 7;
    int EN = E + N;
    bool valid = k < EN;
    if (!valid) k = 0;
    int src, dst;
    if (k < E) { src = __ldg(ei + k); dst = __ldg(ei + E + k); }
    else       { src = dst = k - E; }

    float ex = lrelu_exp(__ldg(ASRC + (size_t)src * 8 + l) + __ldg(ADST + (size_t)dst * 8 + l));
    float a  = __fdividef(ex, __ldg(DEN + (size_t)dst * 8 + l));

    const uint4* xs = reinterpret_cast<const uint4*>(XH) + (size_t)src * 32;
    float acc[8];
    #pragma unroll
    for (int i = 0; i < 8; i++) acc[i] = 0.f;

    #pragma unroll
    for (int j = 0; j < 4; j++) {
        float al = __shfl_sync(0xffffffffu, a, (l >> 2) + 2 * j, 8);
        uint4 u = __ldg(xs + l + 8 * j);
        float2 f0 = __half22float2(*reinterpret_cast<__half2*>(&u.x));
        float2 f1 = __half22float2(*reinterpret_cast<__half2*>(&u.y));
        float2 f2 = __half22float2(*reinterpret_cast<__half2*>(&u.z));
        float2 f3 = __half22float2(*reinterpret_cast<__half2*>(&u.w));
        acc[0] += al * f0.x; acc[1] += al * f0.y;
        acc[2] += al * f1.x; acc[3] += al * f1.y;
        acc[4] += al * f2.x; acc[5] += al * f2.y;
        acc[6] += al * f3.x; acc[7] += al * f3.y;
    }
    #pragma unroll
    for (int i = 0; i < 8; i++) acc[i] += __shfl_xor_sync(0xffffffffu, acc[i], 4);
    // lane l writes dims (l&3)*8 + (l>>2)*4 .. +4
    float4 v = (l < 4) ? make_float4(acc[0], acc[1], acc[2], acc[3])
                       : make_float4(acc[4], acc[5], acc[6], acc[7]);
    if (valid) red_add_v4(AGG + (size_t)dst * 32 + (l & 3) * 8 + (l >> 2) * 4, v);
}

// ---------------- aggregate layer 2: 4 lanes/edge; single red.v4 per lane ----------------
__global__ void aggregate2_kernel(const int* __restrict__ ei, int E, int N,
                                  const __half* __restrict__ XH,
                                  const float* __restrict__ ASRC, const float* __restrict__ ADST,
                                  const float* __restrict__ DEN, float* __restrict__ AGG) {
    int t = blockIdx.x * blockDim.x + threadIdx.x;
    int k = t >> 2;
    int l = t & 3;
    int EN = E + N;
    bool valid = k < EN;
    if (!valid) k = 0;
    int src, dst;
    if (k < E) { src = __ldg(ei + k); dst = __ldg(ei + E + k); }
    else       { src = dst = k - E; }

    float ex0 = lrelu_exp(__ldg(ASRC + (size_t)src * 8 + l) + __ldg(ADST + (size_t)dst * 8 + l));
    float ex1 = lrelu_exp(__ldg(ASRC + (size_t)src * 8 + l + 4) + __ldg(ADST + (size_t)dst * 8 + l + 4));
    float a0 = __fdividef(ex0, __ldg(DEN + (size_t)dst * 8 + l));
    float a1 = __fdividef(ex1, __ldg(DEN + (size_t)dst * 8 + l + 4));

    const uint4* xs = reinterpret_cast<const uint4*>(XH) + (size_t)src * 16;
    float acc[8];
    #pragma unroll
    for (int i = 0; i < 8; i++) acc[i] = 0.f;

    #pragma unroll
    for (int j = 0; j < 4; j++) {
        float al;
        if (j == 0)      al = __shfl_sync(0xffffffffu, a0, (l >> 1),     4);
        else if (j == 1) al = __shfl_sync(0xffffffffu, a0, (l >> 1) + 2, 4);
        else if (j == 2) al = __shfl_sync(0xffffffffu, a1, (l >> 1),     4);
        else             al = __shfl_sync(0xffffffffu, a1, (l >> 1) + 2, 4);
        uint4 u = __ldg(xs + l + 4 * j);
        float2 f0 = __half22float2(*reinterpret_cast<__half2*>(&u.x));
        float2 f1 = __half22float2(*reinterpret_cast<__half2*>(&u.y));
        float2 f2 = __half22float2(*reinterpret_cast<__half2*>(&u.z));
        float2 f3 = __half22float2(*reinterpret_cast<__half2*>(&u.w));
        acc[0] += al * f0.x; acc[1] += al * f0.y;
        acc[2] += al * f1.x; acc[3] += al * f1.y;
        acc[4] += al * f2.x; acc[5] += al * f2.y;
        acc[6] += al * f3.x; acc[7] += al * f3.y;
    }
    #pragma unroll
    for (int i = 0; i < 8; i++) acc[i] += __shfl_xor_sync(0xffffffffu, acc[i], 2);
    // lane l writes dims (l&1)*8 + (l>>1)*4 .. +4
    float4 v = (l < 2) ? make_float4(acc[0], acc[1], acc[2], acc[3])
                       : make_float4(acc[4], acc[5], acc[6], acc[7]);
    if (valid) red_add_v4(AGG + (size_t)dst * 16 + (l & 1) * 8 + (l >> 1) * 4, v);
}

// ---------------- finalize layer 2 ----------------
__global__ void finalize2_kernel(const float* __restrict__ agg, const float* __restrict__ b,
                                 float* __restrict__ outLsm, float* __restrict__ outLogits,
                                 int N, int writeLogits) {
    int gid = blockIdx.x * blockDim.x + threadIdx.x;
    int n = gid >> 4, c = gid & 15;
    bool valid = n < N;
    float l = 0.f;
    if (valid) l = agg[gid] * 0.125f + __ldg(b + c);
    float m = l;
    #pragma unroll
    for (int s = 8; s > 0; s >>= 1) m = fmaxf(m, __shfl_xor_sync(0xffffffffu, m, s));
    float e = __expf(l - m);
    float se = e;
    #pragma unroll
    for (int s = 8; s > 0; s >>= 1) se += __shfl_xor_sync(0xffffffffu, se, s);
    if (valid) {
        outLsm[gid] = l - m - logf(se);
        if (writeLogits) outLogits[gid] = l;
    }
}

// ---------------- host launcher ----------------
extern "C" void kernel_launch(void* const* d_in, const int* in_sizes, int n_in,
                              void* d_out, int out_size) {
    const float* x   = (const float*)d_in[0];
    const int*   ei  = (const int*)d_in[1];
    const float* W1  = (const float*)d_in[2];
    const float* as1 = (const float*)d_in[3];
    const float* ad1 = (const float*)d_in[4];
    const float* b1  = (const float*)d_in[5];
    const float* W2  = (const float*)d_in[6];
    const float* as2 = (const float*)d_in[7];
    const float* ad2 = (const float*)d_in[8];
    const float* b2  = (const float*)d_in[9];

    int N  = in_sizes[0] / 128;
    int E  = in_sizes[1] / 2;
    int EN = E + N;
    float* out = (float*)d_out;

    void *xh1, *xh2, *agg1, *agg2, *asrc, *adst, *den;
    cudaGetSymbolAddress(&xh1,  g_xh1);
    cudaGetSymbolAddress(&xh2,  g_xh2);
    cudaGetSymbolAddress(&agg1, g_agg1);
    cudaGetSymbolAddress(&agg2, g_agg2);
    cudaGetSymbolAddress(&asrc, g_asrc);
    cudaGetSymbolAddress(&adst, g_adst);
    cudaGetSymbolAddress(&den,  g_den);

    float* den1 = (float*)den;
    float* den2 = (float*)den + (size_t)N * 8;

    const int smem1 = (128 * (64 + 8) + 64 * 72) * 2;   // 27648 B
    const int smem2 = (128 * (32 + 8) + 32 * 72) * 2;   // 14848 B
    cudaFuncSetAttribute(gemm_att_kernel<128, 256, 32, 64, false>,
                         cudaFuncAttributeMaxDynamicSharedMemorySize, smem1);
    cudaFuncSetAttribute(gemm_att_kernel<32, 128, 16, 32, true>,
                         cudaFuncAttributeMaxDynamicSharedMemorySize, smem2);

    // 1: zero everything
    zero_all_kernel<<<(N * 32 + 255) / 256, 256>>>((float*)den, (float*)agg1, (float*)agg2, N);

    // ---- layer 1 ----
    gemm_att_kernel<128, 256, 32, 64, false><<<dim3((N + 127) / 128, 4), 256, smem1>>>(
        x, W1, as1, ad1, nullptr, (__half*)xh1, (float*)asrc, (float*)adst, N);        // 2
    den_kernel<<<(EN + 255) / 256, 256>>>(ei, E, N, (float*)asrc, (float*)adst, den1); // 3
    aggregate1_kernel<<<((size_t)EN * 8 + 255) / 256, 256>>>(
        ei, E, N, (__half*)xh1, (float*)asrc, (float*)adst, den1, (float*)agg1);       // 4 <- profiled

    // ---- layer 2 ----
    gemm_att_kernel<32, 128, 16, 32, true><<<dim3((N + 127) / 128, 2), 256, smem2>>>(
        (float*)agg1, W2, as2, ad2, b1, (__half*)xh2, (float*)asrc, (float*)adst, N);  // 5
    den_kernel<<<(EN + 255) / 256, 256>>>(ei, E, N, (float*)asrc, (float*)adst, den2); // 6
    aggregate2_kernel<<<((size_t)EN * 4 + 255) / 256, 256>>>(
        ei, E, N, (__half*)xh2, (float*)asrc, (float*)adst, den2, (float*)agg2);       // 7

    int wl = (out_size >= 2 * N * 16) ? 1 : 0;
    finalize2_kernel<<<(N * 16 + 127) / 128, 128>>>((float*)agg2, b2,
                                                    out, out + (size_t)N * 16, N, wl); // 8
}